// round 1
// baseline (speedup 1.0000x reference)
#include <cuda_runtime.h>
#include <cstdint>
#include <math.h>

// Problem constants
#define NB   2
#define TT   4096
#define NH   16
#define ND   64
#define HD   1024           // NH*ND
#define DMOD 1024
#define MROWS (NB*TT)       // 8192
#define PHASE_SCALE 10.0f

#define LCH  64             // chunk length for the scan
#define NCH  64             // number of chunks (LCH*NCH == TT)

// Scratch (device globals: no allocation allowed in kernel_launch)
__device__ float  g_K [MROWS * HD];    // k_real = x @ Wk
__device__ float  g_V [MROWS * HD];    // v      = x @ Wv
__device__ float  g_OH[MROWS * HD];    // gated holographic output (pre-Wo)
__device__ float4 g_part[NB * NH * NCH * ND]; // per-chunk partial sums (Pre,Pim,Are,Aim)

typedef unsigned long long ull;

__device__ __forceinline__ ull pack_dup(float a) {
    ull r; asm("mov.b64 %0, {%1, %1};" : "=l"(r) : "f"(a)); return r;
}
__device__ __forceinline__ ull pack2(float lo, float hi) {
    ull r; asm("mov.b64 %0, {%1, %2};" : "=l"(r) : "f"(lo), "f"(hi)); return r;
}
__device__ __forceinline__ float2 unpack2(ull v) {
    float2 r; asm("mov.b64 {%0, %1}, %2;" : "=f"(r.x), "=f"(r.y) : "l"(v)); return r;
}
__device__ __forceinline__ void fma2(ull& acc, ull a, ull b) {
    asm("fma.rn.f32x2 %0, %1, %2, %0;" : "+l"(acc) : "l"(a), "l"(b));
}

// ---------------------------------------------------------------------------
// FP32 GEMM, C[M,N] = A[M,K] @ W[K,N], row-major, using packed f32x2 FFMA2.
// 128x128 block tile, BK=8, 256 threads, 8x8 per-thread tile (n in pairs).
// ---------------------------------------------------------------------------
__global__ __launch_bounds__(256, 2)
void sgemm128(const float* __restrict__ A, const float* __restrict__ W,
              float* __restrict__ C, int M, int N, int K)
{
    __shared__ float As[8][128];
    __shared__ float Bs[8][128];

    const int tid = threadIdx.x;
    const int tx = tid & 15;        // 0..15 -> n groups
    const int ty = tid >> 4;        // 0..15 -> m groups
    const int bm = blockIdx.y * 128;
    const int bn = blockIdx.x * 128;

    // global->smem staging: A tile 128x8 (one float4 per thread), B tile 8x128
    const int arow = tid >> 1;              // 0..127
    const int acol = (tid & 1) * 4;         // 0 or 4
    const int brow = tid >> 5;              // 0..7
    const int bcol = (tid & 31) * 4;        // 0..124

    const float* Ap = A + (size_t)(bm + arow) * K + acol;
    const float* Bp = W + (size_t)brow * N + bn + bcol;

    ull acc[8][4];
    #pragma unroll
    for (int i = 0; i < 8; i++)
        #pragma unroll
        for (int j = 0; j < 4; j++) acc[i][j] = 0ull;

    for (int k0 = 0; k0 < K; k0 += 8) {
        float4 a4 = *(const float4*)(Ap + k0);
        float4 b4 = *(const float4*)(Bp + (size_t)k0 * N);
        __syncthreads();
        As[acol + 0][arow] = a4.x;
        As[acol + 1][arow] = a4.y;
        As[acol + 2][arow] = a4.z;
        As[acol + 3][arow] = a4.w;
        *(float4*)&Bs[brow][bcol] = b4;
        __syncthreads();

        #pragma unroll
        for (int k = 0; k < 8; k++) {
            float4 a0 = *(const float4*)&As[k][ty * 4];
            float4 a1 = *(const float4*)&As[k][ty * 4 + 64];
            float4 b0 = *(const float4*)&Bs[k][tx * 4];
            float4 b1 = *(const float4*)&Bs[k][tx * 4 + 64];
            ull bp[4];
            bp[0] = pack2(b0.x, b0.y);
            bp[1] = pack2(b0.z, b0.w);
            bp[2] = pack2(b1.x, b1.y);
            bp[3] = pack2(b1.z, b1.w);
            float av[8] = {a0.x, a0.y, a0.z, a0.w, a1.x, a1.y, a1.z, a1.w};
            #pragma unroll
            for (int mi = 0; mi < 8; mi++) {
                ull ap = pack_dup(av[mi]);
                #pragma unroll
                for (int nj = 0; nj < 4; nj++) fma2(acc[mi][nj], ap, bp[nj]);
            }
        }
    }

    #pragma unroll
    for (int mi = 0; mi < 8; mi++) {
        int m = bm + ty * 4 + ((mi < 4) ? mi : 60 + mi);   // mi=4..7 -> +64..+67
        float* Cp = C + (size_t)m * N + bn + tx * 4;
        float2 p0 = unpack2(acc[mi][0]);
        float2 p1 = unpack2(acc[mi][1]);
        *(float4*)Cp = make_float4(p0.x, p0.y, p1.x, p1.y);
        p0 = unpack2(acc[mi][2]);
        p1 = unpack2(acc[mi][3]);
        *(float4*)(Cp + 64) = make_float4(p0.x, p0.y, p1.x, p1.y);
    }
}

// ---------------------------------------------------------------------------
// Scan pass A: per-chunk partial complex sums for both paths.
// grid: NB*NH*(NCH/4) blocks, 256 threads = 64 d-lanes x 4 chunks
// ---------------------------------------------------------------------------
__global__ void scan_partials(const float* __restrict__ freqs)
{
    const int tid = threadIdx.x;
    const int d   = tid & 63;
    const int sub = tid >> 6;            // 0..3
    const int bh  = blockIdx.x >> 4;     // NCH/4 = 16 groups per (b,h)
    const int cg  = blockIdx.x & 15;
    const int c   = cg * 4 + sub;
    const int b   = bh >> 4;
    const int h   = bh & 15;

    const float f = freqs[h * ND + d];
    const int t0 = c * LCH;

    // previous key phasor (binder = conj(k_{t-1})); zero at t=0
    float pc = 0.f, ps = 0.f;
    if (t0 > 0) {
        float th = PHASE_SCALE * g_K[((size_t)(b * TT + t0 - 1)) * HD + h * ND + d];
        sincosf(th, &ps, &pc);
    }

    float Pre = 0.f, Pim = 0.f, Are = 0.f, Aim = 0.f;
    size_t base = ((size_t)(b * TT + t0)) * HD + h * ND + d;
    for (int i = 0; i < LCH; i++) {
        float v  = g_V[base];
        float kr = g_K[base];
        base += HD;
        // assoc: mem += v * conj(k_prev)
        Are += v * pc;
        Aim -= v * ps;
        float ks, kc;
        sincosf(PHASE_SCALE * kr, &ks, &kc);
        pc = kc; ps = ks;
        // pos: mem += v * rotor_t,  theta = fl(t * f) (matches reference)
        float sr, cr;
        sincosf((float)(t0 + i) * f, &sr, &cr);
        Pre += v * cr;
        Pim += v * sr;
    }
    g_part[((size_t)bh * NCH + c) * ND + d] = make_float4(Pre, Pim, Are, Aim);
}

// ---------------------------------------------------------------------------
// Scan pass B: exclusive offset from earlier chunks, rescan chunk, emit gated
// output  out = (g0 * out_pos + g1 * out_assoc) / sqrt(t+1)
// ---------------------------------------------------------------------------
__global__ void scan_final(const float* __restrict__ freqs,
                           const float* __restrict__ gate)
{
    const int tid = threadIdx.x;
    const int d   = tid & 63;
    const int sub = tid >> 6;
    const int bh  = blockIdx.x >> 4;
    const int cg  = blockIdx.x & 15;
    const int c   = cg * 4 + sub;
    const int b   = bh >> 4;
    const int h   = bh & 15;

    const float f  = freqs[h * ND + d];
    const float g0 = gate[2 * h];
    const float g1 = gate[2 * h + 1];
    const int t0 = c * LCH;

    // exclusive prefix over chunk partials (small, L2-resident)
    float Pre = 0.f, Pim = 0.f, Are = 0.f, Aim = 0.f;
    const float4* pp = g_part + ((size_t)bh * NCH * ND + d);
    for (int cc = 0; cc < c; cc++) {
        float4 p = pp[(size_t)cc * ND];
        Pre += p.x; Pim += p.y; Are += p.z; Aim += p.w;
    }

    float pc = 0.f, ps = 0.f;
    if (t0 > 0) {
        float th = PHASE_SCALE * g_K[((size_t)(b * TT + t0 - 1)) * HD + h * ND + d];
        sincosf(th, &ps, &pc);
    }

    size_t base = ((size_t)(b * TT + t0)) * HD + h * ND + d;
    for (int i = 0; i < LCH; i++) {
        float v  = g_V[base];
        float kr = g_K[base];
        // assoc accumulate, then retrieve with current key phasor
        Are += v * pc;
        Aim -= v * ps;
        float ks, kc;
        sincosf(PHASE_SCALE * kr, &ks, &kc);
        float oa = Are * kc - Aim * ks;       // Re(mem_a * k_t)
        pc = kc; ps = ks;
        // pos accumulate, retrieve with conj(rotor_t)
        float sr, cr;
        sincosf((float)(t0 + i) * f, &sr, &cr);
        Pre += v * cr;
        Pim += v * sr;
        float op = Pre * cr + Pim * sr;       // Re(mem_p * conj(rotor_t))
        int t = t0 + i;
        g_OH[base] = (g0 * op + g1 * oa) * rsqrtf((float)(t + 1));
        base += HD;
    }
}

// ---------------------------------------------------------------------------
extern "C" void kernel_launch(void* const* d_in, const int* in_sizes, int n_in,
                              void* d_out, int out_size)
{
    const float* x     = (const float*)d_in[0];
    const float* Wk    = (const float*)d_in[1];
    const float* Wv    = (const float*)d_in[2];
    const float* Wo    = (const float*)d_in[3];
    const float* gate  = (const float*)d_in[4];
    const float* freqs = (const float*)d_in[5];
    float* out = (float*)d_out;

    float *pK, *pV, *pOH;
    cudaGetSymbolAddress((void**)&pK,  g_K);
    cudaGetSymbolAddress((void**)&pV,  g_V);
    cudaGetSymbolAddress((void**)&pOH, g_OH);

    dim3 ggemm(HD / 128, MROWS / 128);   // (8, 64)
    sgemm128<<<ggemm, 256>>>(x, Wk, pK, MROWS, HD, DMOD);
    sgemm128<<<ggemm, 256>>>(x, Wv, pV, MROWS, HD, DMOD);

    int nscan = NB * NH * (NCH / 4);     // 512 blocks
    scan_partials<<<nscan, 256>>>(freqs);
    scan_final<<<nscan, 256>>>(freqs, gate);

    sgemm128<<<ggemm, 256>>>(pOH, Wo, out, MROWS, DMOD, HD);
}

// round 7
// speedup vs baseline: 1.9497x; 1.9497x over previous
#include <cuda_runtime.h>
#include <cuda_bf16.h>
#include <cstdint>
#include <math.h>

// Problem constants
#define NB   2
#define TT   4096
#define NH   16
#define ND   64
#define HD   1024
#define DMOD 1024
#define MROWS (NB*TT)       // 8192
#define PHASE_SCALE 10.0f
#define LCH  64
#define NCH  64
#define GK   1024
#define GN   1024

// ---------------- scratch (device globals; no allocs allowed) ----------------
__device__ float  g_K [MROWS * HD];
__device__ float  g_V [MROWS * HD];
__device__ float  g_OH[MROWS * HD];
__device__ float4 g_part[NB * NH * NCH * ND];
__device__ unsigned short g_ahi[MROWS * HD];     // bf16 hi of A operand (x / OH)
__device__ unsigned short g_alo[MROWS * HD];     // bf16 lo
__device__ unsigned short g_wT[6][HD * DMOD];    // WkT hi/lo, WvT hi/lo, WoT hi/lo

// ---------------- PTX helpers (baseline sm_80+ features only) ----------------
__device__ __forceinline__ uint32_t s2u(const void* p) {
    uint32_t a;
    asm("{ .reg .u64 t; cvta.to.shared.u64 t, %1; cvt.u32.u64 %0, t; }" : "=r"(a) : "l"(p));
    return a;
}
__device__ __forceinline__ void cp16(uint32_t s, const void* g) {
    asm volatile("cp.async.cg.shared.global [%0], [%1], 16;" :: "r"(s), "l"(g));
}
__device__ __forceinline__ void cp_commit() {
    asm volatile("cp.async.commit_group;" ::: "memory");
}
template <int N>
__device__ __forceinline__ void cp_wait() {
    asm volatile("cp.async.wait_group %0;" :: "n"(N) : "memory");
}
__device__ __forceinline__ void ldsm4(uint32_t* r, uint32_t addr) {
    asm volatile("ldmatrix.sync.aligned.m8n8.x4.shared.b16 {%0,%1,%2,%3}, [%4];"
        : "=r"(r[0]), "=r"(r[1]), "=r"(r[2]), "=r"(r[3]) : "r"(addr));
}
// NON-trans x2: B tile stored [N,K] row-major == col-major [K,N] operand;
// non-trans ldmatrix yields lane i = consecutive-k pair at n=i/4 (the
// required b-fragment). The .trans variant was the round-6 bug.
__device__ __forceinline__ void ldsm2(uint32_t* r, uint32_t addr) {
    asm volatile("ldmatrix.sync.aligned.m8n8.x2.shared.b16 {%0,%1}, [%2];"
        : "=r"(r[0]), "=r"(r[1]) : "r"(addr));
}
__device__ __forceinline__ void mma16816(float* c, const uint32_t* a, const uint32_t* b) {
    asm volatile("mma.sync.aligned.m16n8k16.row.col.f32.bf16.bf16.f32 "
        "{%0,%1,%2,%3}, {%4,%5,%6,%7}, {%8,%9}, {%0,%1,%2,%3};"
        : "+f"(c[0]), "+f"(c[1]), "+f"(c[2]), "+f"(c[3])
        : "r"(a[0]), "r"(a[1]), "r"(a[2]), "r"(a[3]), "r"(b[0]), "r"(b[1]));
}

// ---------------------------------------------------------------------------
// bf16x3 tensor-core GEMM via mma.sync:  C[M,N] = A[M,K] @ B[N,K]^T
// fp32-accurate: hi*hi + hi*lo + lo*hi (lo*lo dropped, ~2^-18 relative).
// 128x128 block tile, BK=32, 256 threads, 2-stage cp.async pipeline.
// SMEM rows padded to 80B -> conflict-free ldmatrix without swizzle.
// ---------------------------------------------------------------------------
#define BM 128
#define BN 128
#define BK 32
#define ROWB 80                       // 64B data + 16B pad
#define TILE_B  (BM * ROWB)           // 10240 B
#define STAGE_B (4 * TILE_B)          // Ahi, Alo, Bhi, Blo = 40960 B
#define GEMM_SMEM (2 * STAGE_B)       // 81920 B
#define NIT (GK / BK)                 // 32

__global__ __launch_bounds__(256, 2)
void gemm_bf16x3(const unsigned short* __restrict__ Ahi,
                 const unsigned short* __restrict__ Alo,
                 const unsigned short* __restrict__ Bhi,
                 const unsigned short* __restrict__ Blo,
                 float* __restrict__ C)
{
    extern __shared__ __align__(128) unsigned char smem[];
    const uint32_t sb = s2u(smem);

    const int tid  = threadIdx.x;
    const int lane = tid & 31;
    const int warp = tid >> 5;
    const int bm = blockIdx.y * BM;
    const int bn = blockIdx.x * BN;
    const int m0 = (warp >> 2) * 64;       // warp M offset within tile
    const int n0 = (warp & 3) * 32;        // warp N offset within tile

    const unsigned short* srcs[4] = {
        Ahi + (size_t)bm * GK, Alo + (size_t)bm * GK,
        Bhi + (size_t)bn * GK, Blo + (size_t)bn * GK };

    // per-thread staging slots: 2 chunks per tile per thread
    const int r0 = (tid + 0)   >> 2, c0i = (tid + 0)   & 3;
    const int r1 = (tid + 256) >> 2, c1i = (tid + 256) & 3;

    auto load_stage = [&](int s, int k0) {
        uint32_t base = sb + s * STAGE_B;
        #pragma unroll
        for (int t = 0; t < 4; t++) {
            cp16(base + t * TILE_B + r0 * ROWB + c0i * 16,
                 srcs[t] + (size_t)r0 * GK + k0 + c0i * 8);
            cp16(base + t * TILE_B + r1 * ROWB + c1i * 16,
                 srcs[t] + (size_t)r1 * GK + k0 + c1i * 8);
        }
    };

    float acc[4][4][4];
    #pragma unroll
    for (int i = 0; i < 4; i++)
        #pragma unroll
        for (int j = 0; j < 4; j++)
            #pragma unroll
            for (int k = 0; k < 4; k++) acc[i][j][k] = 0.f;

    load_stage(0, 0);
    cp_commit();

    // precomputed per-lane ldmatrix address components
    const uint32_t a_row  = m0 + (lane & 15);
    const uint32_t a_coff = (lane >> 4) * 16;        // bytes
    const uint32_t b_row  = n0 + (lane & 7);
    const uint32_t b_coff = ((lane >> 3) & 1) * 16;  // bytes

    for (int it = 0; it < NIT; it++) {
        if (it + 1 < NIT) {
            load_stage((it + 1) & 1, (it + 1) * BK);
            cp_commit();
            cp_wait<1>();
        } else {
            cp_wait<0>();
        }
        __syncthreads();

        const uint32_t stg = sb + (it & 1) * STAGE_B;
        const uint32_t sAh = stg;
        const uint32_t sAl = stg + TILE_B;
        const uint32_t sBh = stg + 2 * TILE_B;
        const uint32_t sBl = stg + 3 * TILE_B;

        #pragma unroll
        for (int kk = 0; kk < 2; kk++) {
            const uint32_t kb = kk * 32;            // byte offset of this k16
            uint32_t bh[4][2], bl[4][2];
            #pragma unroll
            for (int nt = 0; nt < 4; nt++) {
                uint32_t ba = (b_row + nt * 8) * ROWB + kb + b_coff;
                ldsm2(bh[nt], sBh + ba);
                ldsm2(bl[nt], sBl + ba);
            }
            #pragma unroll
            for (int mt = 0; mt < 4; mt++) {
                uint32_t ah[4], al[4];
                uint32_t aa = (a_row + mt * 16) * ROWB + kb + a_coff;
                ldsm4(ah, sAh + aa);
                ldsm4(al, sAl + aa);
                #pragma unroll
                for (int nt = 0; nt < 4; nt++) {
                    mma16816(acc[mt][nt], ah, bh[nt]);   // hi*hi
                    mma16816(acc[mt][nt], ah, bl[nt]);   // hi*lo
                    mma16816(acc[mt][nt], al, bh[nt]);   // lo*hi
                }
            }
        }
        __syncthreads();
    }

    // epilogue: c layout m16n8 -> thread (lane/4, (lane%4)*2), rows +0/+8
    #pragma unroll
    for (int mt = 0; mt < 4; mt++) {
        const int m = bm + m0 + mt * 16 + (lane >> 2);
        #pragma unroll
        for (int nt = 0; nt < 4; nt++) {
            const int n = bn + n0 + nt * 8 + (lane & 3) * 2;
            *(float2*)&C[(size_t)m * GN + n] =
                make_float2(acc[mt][nt][0], acc[mt][nt][1]);
            *(float2*)&C[(size_t)(m + 8) * GN + n] =
                make_float2(acc[mt][nt][2], acc[mt][nt][3]);
        }
    }
}

// ---------------------------------------------------------------------------
// fp32 -> bf16 hi/lo split (vectorized)
// ---------------------------------------------------------------------------
__device__ __forceinline__ unsigned short bf_hi(float x, float& rem) {
    __nv_bfloat16 h = __float2bfloat16_rn(x);
    rem = x - __bfloat162float(h);
    return *reinterpret_cast<unsigned short*>(&h);
}
__device__ __forceinline__ unsigned short bf_of(float x) {
    __nv_bfloat16 h = __float2bfloat16_rn(x);
    return *reinterpret_cast<unsigned short*>(&h);
}

__global__ void split_hilo(const float* __restrict__ src,
                           unsigned short* __restrict__ hi,
                           unsigned short* __restrict__ lo, int n4)
{
    int i = blockIdx.x * blockDim.x + threadIdx.x;
    if (i >= n4) return;
    float4 v = ((const float4*)src)[i];
    float r0, r1, r2, r3;
    unsigned short h0 = bf_hi(v.x, r0), h1 = bf_hi(v.y, r1);
    unsigned short h2 = bf_hi(v.z, r2), h3 = bf_hi(v.w, r3);
    ((uint2*)hi)[i] = make_uint2((uint32_t)h0 | ((uint32_t)h1 << 16),
                                (uint32_t)h2 | ((uint32_t)h3 << 16));
    unsigned short l0 = bf_of(r0), l1 = bf_of(r1), l2 = bf_of(r2), l3 = bf_of(r3);
    ((uint2*)lo)[i] = make_uint2((uint32_t)l0 | ((uint32_t)l1 << 16),
                                (uint32_t)l2 | ((uint32_t)l3 << 16));
}

// W [K,N] fp32 -> WT [N,K] bf16 hi/lo
__global__ void wsplitT(const float* __restrict__ W,
                        unsigned short* __restrict__ hiT,
                        unsigned short* __restrict__ loT)
{
    __shared__ float tile[32][33];
    int n0 = blockIdx.x * 32, k0 = blockIdx.y * 32;
    int tx = threadIdx.x, ty = threadIdx.y;
    for (int r = ty; r < 32; r += 8)
        tile[r][tx] = W[(size_t)(k0 + r) * GN + n0 + tx];
    __syncthreads();
    for (int r = ty; r < 32; r += 8) {
        float v = tile[tx][r];                    // W[k0+tx][n0+r]
        size_t o = (size_t)(n0 + r) * GK + k0 + tx;
        float rem;
        hiT[o] = bf_hi(v, rem);
        loT[o] = bf_of(rem);
    }
}

// ---------------------------------------------------------------------------
// Scan pass A: per-chunk partial complex sums
// ---------------------------------------------------------------------------
__global__ void scan_partials(const float* __restrict__ freqs)
{
    const int tid = threadIdx.x;
    const int d   = tid & 63;
    const int sub = tid >> 6;
    const int bh  = blockIdx.x >> 4;
    const int cg  = blockIdx.x & 15;
    const int c   = cg * 4 + sub;
    const int b   = bh >> 4;
    const int h   = bh & 15;

    const float f = freqs[h * ND + d];
    const int t0 = c * LCH;

    float pc = 0.f, ps = 0.f;
    if (t0 > 0) {
        float th = PHASE_SCALE * g_K[((size_t)(b * TT + t0 - 1)) * HD + h * ND + d];
        sincosf(th, &ps, &pc);
    }

    float Pre = 0.f, Pim = 0.f, Are = 0.f, Aim = 0.f;
    size_t base = ((size_t)(b * TT + t0)) * HD + h * ND + d;
    for (int i = 0; i < LCH; i++) {
        float v  = g_V[base];
        float kr = g_K[base];
        base += HD;
        Are += v * pc;
        Aim -= v * ps;
        float ks, kc;
        sincosf(PHASE_SCALE * kr, &ks, &kc);
        pc = kc; ps = ks;
        float sr, cr;
        sincosf((float)(t0 + i) * f, &sr, &cr);
        Pre += v * cr;
        Pim += v * sr;
    }
    g_part[((size_t)bh * NCH + c) * ND + d] = make_float4(Pre, Pim, Are, Aim);
}

// ---------------------------------------------------------------------------
// Scan pass B: exclusive offsets + final gated output
// ---------------------------------------------------------------------------
__global__ void scan_final(const float* __restrict__ freqs,
                           const float* __restrict__ gate)
{
    const int tid = threadIdx.x;
    const int d   = tid & 63;
    const int sub = tid >> 6;
    const int bh  = blockIdx.x >> 4;
    const int cg  = blockIdx.x & 15;
    const int c   = cg * 4 + sub;
    const int b   = bh >> 4;
    const int h   = bh & 15;

    const float f  = freqs[h * ND + d];
    const float g0 = gate[2 * h];
    const float g1 = gate[2 * h + 1];
    const int t0 = c * LCH;

    float Pre = 0.f, Pim = 0.f, Are = 0.f, Aim = 0.f;
    const float4* pp = g_part + ((size_t)bh * NCH * ND + d);
    for (int cc = 0; cc < c; cc++) {
        float4 p = pp[(size_t)cc * ND];
        Pre += p.x; Pim += p.y; Are += p.z; Aim += p.w;
    }

    float pc = 0.f, ps = 0.f;
    if (t0 > 0) {
        float th = PHASE_SCALE * g_K[((size_t)(b * TT + t0 - 1)) * HD + h * ND + d];
        sincosf(th, &ps, &pc);
    }

    size_t base = ((size_t)(b * TT + t0)) * HD + h * ND + d;
    for (int i = 0; i < LCH; i++) {
        float v  = g_V[base];
        float kr = g_K[base];
        Are += v * pc;
        Aim -= v * ps;
        float ks, kc;
        sincosf(PHASE_SCALE * kr, &ks, &kc);
        float oa = Are * kc - Aim * ks;
        pc = kc; ps = ks;
        float sr, cr;
        sincosf((float)(t0 + i) * f, &sr, &cr);
        Pre += v * cr;
        Pim += v * sr;
        float op = Pre * cr + Pim * sr;
        int t = t0 + i;
        g_OH[base] = (g0 * op + g1 * oa) * rsqrtf((float)(t + 1));
        base += HD;
    }
}

// ---------------------------------------------------------------------------
extern "C" void kernel_launch(void* const* d_in, const int* in_sizes, int n_in,
                              void* d_out, int out_size)
{
    const float* x     = (const float*)d_in[0];
    const float* Wk    = (const float*)d_in[1];
    const float* Wv    = (const float*)d_in[2];
    const float* Wo    = (const float*)d_in[3];
    const float* gate  = (const float*)d_in[4];
    const float* freqs = (const float*)d_in[5];
    float* out = (float*)d_out;

    float *pK, *pV, *pOH;
    unsigned short *pahi, *palo, *pwT;
    cudaGetSymbolAddress((void**)&pK,   g_K);
    cudaGetSymbolAddress((void**)&pV,   g_V);
    cudaGetSymbolAddress((void**)&pOH,  g_OH);
    cudaGetSymbolAddress((void**)&pahi, g_ahi);
    cudaGetSymbolAddress((void**)&palo, g_alo);
    cudaGetSymbolAddress((void**)&pwT,  g_wT);

    cudaFuncSetAttribute(gemm_bf16x3,
                         cudaFuncAttributeMaxDynamicSharedMemorySize, GEMM_SMEM);

    const int WSZ = HD * DMOD;
    unsigned short* wkh = pwT + 0*WSZ; unsigned short* wkl = pwT + 1*WSZ;
    unsigned short* wvh = pwT + 2*WSZ; unsigned short* wvl = pwT + 3*WSZ;
    unsigned short* woh = pwT + 4*WSZ; unsigned short* wol = pwT + 5*WSZ;

    const int n4 = MROWS * HD / 4;
    split_hilo<<<(n4 + 255) / 256, 256>>>(x, pahi, palo, n4);
    wsplitT<<<dim3(32, 32), dim3(32, 8)>>>(Wk, wkh, wkl);
    wsplitT<<<dim3(32, 32), dim3(32, 8)>>>(Wv, wvh, wvl);
    wsplitT<<<dim3(32, 32), dim3(32, 8)>>>(Wo, woh, wol);

    dim3 ggemm(GN / BN, MROWS / BM);   // (8, 64)
    gemm_bf16x3<<<ggemm, 256, GEMM_SMEM>>>(pahi, palo, wkh, wkl, pK);
    gemm_bf16x3<<<ggemm, 256, GEMM_SMEM>>>(pahi, palo, wvh, wvl, pV);

    int nscan = NB * NH * (NCH / 4);     // 512
    scan_partials<<<nscan, 256>>>(freqs);
    scan_final<<<nscan, 256>>>(freqs, gate);

    split_hilo<<<(n4 + 255) / 256, 256>>>(pOH, pahi, palo, n4);
    gemm_bf16x3<<<ggemm, 256, GEMM_SMEM>>>(pahi, palo, woh, wol, out);
}

// round 8
// speedup vs baseline: 1.9977x; 1.0246x over previous
#include <cuda_runtime.h>
#include <cuda_bf16.h>
#include <cstdint>
#include <math.h>

// Problem constants
#define NB   2
#define TT   4096
#define NH   16
#define ND   64
#define HD   1024
#define DMOD 1024
#define MROWS (NB*TT)       // 8192
#define PHASE_SCALE 10.0f
#define LCH  64
#define NCH  64
#define GK   1024
#define GN   1024

// ---------------- scratch (device globals; no allocs allowed) ----------------
__device__ float  g_K [MROWS * HD];
__device__ float  g_V [MROWS * HD];
__device__ float4 g_part[NB * NH * NCH * ND];
__device__ unsigned short g_ahi[MROWS * HD];     // bf16 hi of A operand (x / OH)
__device__ unsigned short g_alo[MROWS * HD];     // bf16 lo
__device__ unsigned short g_wT[6][HD * DMOD];    // WkT hi/lo, WvT hi/lo, WoT hi/lo

// ---------------- PTX helpers (baseline sm_80+ features only) ----------------
__device__ __forceinline__ uint32_t s2u(const void* p) {
    uint32_t a;
    asm("{ .reg .u64 t; cvta.to.shared.u64 t, %1; cvt.u32.u64 %0, t; }" : "=r"(a) : "l"(p));
    return a;
}
__device__ __forceinline__ void cp16(uint32_t s, const void* g) {
    asm volatile("cp.async.cg.shared.global [%0], [%1], 16;" :: "r"(s), "l"(g));
}
__device__ __forceinline__ void cp_commit() {
    asm volatile("cp.async.commit_group;" ::: "memory");
}
template <int N>
__device__ __forceinline__ void cp_wait() {
    asm volatile("cp.async.wait_group %0;" :: "n"(N) : "memory");
}
__device__ __forceinline__ void ldsm4(uint32_t* r, uint32_t addr) {
    asm volatile("ldmatrix.sync.aligned.m8n8.x4.shared.b16 {%0,%1,%2,%3}, [%4];"
        : "=r"(r[0]), "=r"(r[1]), "=r"(r[2]), "=r"(r[3]) : "r"(addr));
}
// non-trans: B tile stored [N,K] row-major == col-major [K,N] operand
__device__ __forceinline__ void ldsm2(uint32_t* r, uint32_t addr) {
    asm volatile("ldmatrix.sync.aligned.m8n8.x2.shared.b16 {%0,%1}, [%2];"
        : "=r"(r[0]), "=r"(r[1]) : "r"(addr));
}
__device__ __forceinline__ void mma16816(float* c, const uint32_t* a, const uint32_t* b) {
    asm volatile("mma.sync.aligned.m16n8k16.row.col.f32.bf16.bf16.f32 "
        "{%0,%1,%2,%3}, {%4,%5,%6,%7}, {%8,%9}, {%0,%1,%2,%3};"
        : "+f"(c[0]), "+f"(c[1]), "+f"(c[2]), "+f"(c[3])
        : "r"(a[0]), "r"(a[1]), "r"(a[2]), "r"(a[3]), "r"(b[0]), "r"(b[1]));
}

// ---------------------------------------------------------------------------
// bf16x3 tensor-core GEMM via mma.sync:  C[M,N] = A[M,K] @ B[N,K]^T
// hi*hi + hi*lo + lo*hi (lo*lo dropped, ~2^-18 relative).
// 128x128 tile, BK=32, 256 threads, 2-stage cp.async, ONE sync per iter.
// SMEM rows padded to 80B -> conflict-free ldmatrix without swizzle.
// ---------------------------------------------------------------------------
#define BM 128
#define BN 128
#define BK 32
#define ROWB 80                       // 64B data + 16B pad
#define TILE_B  (BM * ROWB)           // 10240 B
#define STAGE_B (4 * TILE_B)          // Ahi, Alo, Bhi, Blo = 40960 B
#define GEMM_SMEM (2 * STAGE_B)       // 81920 B
#define NIT (GK / BK)                 // 32

__global__ __launch_bounds__(256, 2)
void gemm_bf16x3(const unsigned short* __restrict__ Ahi,
                 const unsigned short* __restrict__ Alo,
                 const unsigned short* __restrict__ Bhi,
                 const unsigned short* __restrict__ Blo,
                 float* __restrict__ C)
{
    extern __shared__ __align__(128) unsigned char smem[];
    const uint32_t sb = s2u(smem);

    const int tid  = threadIdx.x;
    const int lane = tid & 31;
    const int warp = tid >> 5;
    const int bm = blockIdx.y * BM;
    const int bn = blockIdx.x * BN;
    const int m0 = (warp >> 2) * 64;       // warp M offset within tile
    const int n0 = (warp & 3) * 32;        // warp N offset within tile

    const unsigned short* srcs[4] = {
        Ahi + (size_t)bm * GK, Alo + (size_t)bm * GK,
        Bhi + (size_t)bn * GK, Blo + (size_t)bn * GK };

    // per-thread staging slots: 2 chunks per tile per thread
    const int r0 = (tid + 0)   >> 2, c0i = (tid + 0)   & 3;
    const int r1 = (tid + 256) >> 2, c1i = (tid + 256) & 3;
    const uint32_t so0 = r0 * ROWB + c0i * 16;
    const uint32_t so1 = r1 * ROWB + c1i * 16;
    const size_t go0 = (size_t)r0 * GK + c0i * 8;
    const size_t go1 = (size_t)r1 * GK + c1i * 8;

    auto load_stage = [&](int s, int k0) {
        uint32_t base = sb + s * STAGE_B;
        #pragma unroll
        for (int t = 0; t < 4; t++) {
            cp16(base + t * TILE_B + so0, srcs[t] + go0 + k0);
            cp16(base + t * TILE_B + so1, srcs[t] + go1 + k0);
        }
        cp_commit();
    };

    float acc[4][4][4];
    #pragma unroll
    for (int i = 0; i < 4; i++)
        #pragma unroll
        for (int j = 0; j < 4; j++)
            #pragma unroll
            for (int k = 0; k < 4; k++) acc[i][j][k] = 0.f;

    // per-lane ldmatrix address components (stage-invariant parts)
    const uint32_t a_off = (m0 + (lane & 15)) * ROWB + (lane >> 4) * 16;
    const uint32_t b_off = (n0 + (lane & 7)) * ROWB + ((lane >> 3) & 1) * 16;

    load_stage(0, 0);

    #pragma unroll 2
    for (int it = 0; it < NIT; it++) {
        cp_wait<0>();
        __syncthreads();
        if (it + 1 < NIT) load_stage((it + 1) & 1, (it + 1) * BK);

        const uint32_t stg = sb + (it & 1) * STAGE_B;
        const uint32_t sAh = stg + a_off;
        const uint32_t sAl = stg + TILE_B + a_off;
        const uint32_t sBh = stg + 2 * TILE_B + b_off;
        const uint32_t sBl = stg + 3 * TILE_B + b_off;

        #pragma unroll
        for (int kk = 0; kk < 2; kk++) {
            const uint32_t kb = kk * 32;            // byte offset of this k16
            uint32_t bh[4][2], bl[4][2];
            #pragma unroll
            for (int nt = 0; nt < 4; nt++) {
                uint32_t ba = nt * (8 * ROWB) + kb;
                ldsm2(bh[nt], sBh + ba);
                ldsm2(bl[nt], sBl + ba);
            }
            #pragma unroll
            for (int mt = 0; mt < 4; mt++) {
                uint32_t ah[4], al[4];
                uint32_t aa = mt * (16 * ROWB) + kb;
                ldsm4(ah, sAh + aa);
                ldsm4(al, sAl + aa);
                #pragma unroll
                for (int nt = 0; nt < 4; nt++) {
                    mma16816(acc[mt][nt], ah, bh[nt]);   // hi*hi
                    mma16816(acc[mt][nt], ah, bl[nt]);   // hi*lo
                    mma16816(acc[mt][nt], al, bh[nt]);   // lo*hi
                }
            }
        }
    }

    // epilogue: c layout m16n8 -> thread (lane/4, (lane%4)*2), rows +0/+8
    #pragma unroll
    for (int mt = 0; mt < 4; mt++) {
        const int m = bm + m0 + mt * 16 + (lane >> 2);
        #pragma unroll
        for (int nt = 0; nt < 4; nt++) {
            const int n = bn + n0 + nt * 8 + (lane & 3) * 2;
            *(float2*)&C[(size_t)m * GN + n] =
                make_float2(acc[mt][nt][0], acc[mt][nt][1]);
            *(float2*)&C[(size_t)(m + 8) * GN + n] =
                make_float2(acc[mt][nt][2], acc[mt][nt][3]);
        }
    }
}

// ---------------------------------------------------------------------------
// fp32 -> bf16 hi/lo split helpers
// ---------------------------------------------------------------------------
__device__ __forceinline__ unsigned short bf_hi(float x, float& rem) {
    __nv_bfloat16 h = __float2bfloat16_rn(x);
    rem = x - __bfloat162float(h);
    return *reinterpret_cast<unsigned short*>(&h);
}
__device__ __forceinline__ unsigned short bf_of(float x) {
    __nv_bfloat16 h = __float2bfloat16_rn(x);
    return *reinterpret_cast<unsigned short*>(&h);
}

__global__ void split_hilo(const float* __restrict__ src,
                           unsigned short* __restrict__ hi,
                           unsigned short* __restrict__ lo, int n4)
{
    int i = blockIdx.x * blockDim.x + threadIdx.x;
    if (i >= n4) return;
    float4 v = ((const float4*)src)[i];
    float r0, r1, r2, r3;
    unsigned short h0 = bf_hi(v.x, r0), h1 = bf_hi(v.y, r1);
    unsigned short h2 = bf_hi(v.z, r2), h3 = bf_hi(v.w, r3);
    ((uint2*)hi)[i] = make_uint2((uint32_t)h0 | ((uint32_t)h1 << 16),
                                (uint32_t)h2 | ((uint32_t)h3 << 16));
    unsigned short l0 = bf_of(r0), l1 = bf_of(r1), l2 = bf_of(r2), l3 = bf_of(r3);
    ((uint2*)lo)[i] = make_uint2((uint32_t)l0 | ((uint32_t)l1 << 16),
                                (uint32_t)l2 | ((uint32_t)l3 << 16));
}

// W [K,N] fp32 -> WT [N,K] bf16 hi/lo; blockIdx.z selects {Wk,Wv,Wo}
__global__ void wsplitT3(const float* __restrict__ W0,
                         const float* __restrict__ W1,
                         const float* __restrict__ W2)
{
    __shared__ float tile[32][33];
    const float* W = (blockIdx.z == 0) ? W0 : (blockIdx.z == 1) ? W1 : W2;
    unsigned short* hiT = &g_wT[2 * blockIdx.z][0];
    unsigned short* loT = &g_wT[2 * blockIdx.z + 1][0];
    int n0 = blockIdx.x * 32, k0 = blockIdx.y * 32;
    int tx = threadIdx.x, ty = threadIdx.y;
    for (int r = ty; r < 32; r += 8)
        tile[r][tx] = W[(size_t)(k0 + r) * GN + n0 + tx];
    __syncthreads();
    for (int r = ty; r < 32; r += 8) {
        float v = tile[tx][r];                    // W[k0+tx][n0+r]
        size_t o = (size_t)(n0 + r) * GK + k0 + tx;
        float rem;
        hiT[o] = bf_hi(v, rem);
        loT[o] = bf_of(rem);
    }
}

// ---------------------------------------------------------------------------
// Scan pass A: per-chunk partial complex sums
// ---------------------------------------------------------------------------
__global__ void scan_partials(const float* __restrict__ freqs)
{
    const int tid = threadIdx.x;
    const int d   = tid & 63;
    const int sub = tid >> 6;
    const int bh  = blockIdx.x >> 4;
    const int cg  = blockIdx.x & 15;
    const int c   = cg * 4 + sub;
    const int b   = bh >> 4;
    const int h   = bh & 15;

    const float f = freqs[h * ND + d];
    const int t0 = c * LCH;

    float pc = 0.f, ps = 0.f;
    if (t0 > 0) {
        float th = PHASE_SCALE * g_K[((size_t)(b * TT + t0 - 1)) * HD + h * ND + d];
        sincosf(th, &ps, &pc);
    }

    float Pre = 0.f, Pim = 0.f, Are = 0.f, Aim = 0.f;
    size_t base = ((size_t)(b * TT + t0)) * HD + h * ND + d;
    for (int i = 0; i < LCH; i++) {
        float v  = g_V[base];
        float kr = g_K[base];
        base += HD;
        Are += v * pc;
        Aim -= v * ps;
        float ks, kc;
        sincosf(PHASE_SCALE * kr, &ks, &kc);
        pc = kc; ps = ks;
        float sr, cr;
        sincosf((float)(t0 + i) * f, &sr, &cr);
        Pre += v * cr;
        Pim += v * sr;
    }
    g_part[((size_t)bh * NCH + c) * ND + d] = make_float4(Pre, Pim, Are, Aim);
}

// ---------------------------------------------------------------------------
// Scan pass B: exclusive offsets + final gated output, written directly as
// bf16 hi/lo (fuses the OH split -> feeds the Wo GEMM without an fp32 pass)
// ---------------------------------------------------------------------------
__global__ void scan_final(const float* __restrict__ freqs,
                           const float* __restrict__ gate)
{
    const int tid = threadIdx.x;
    const int d   = tid & 63;
    const int sub = tid >> 6;
    const int bh  = blockIdx.x >> 4;
    const int cg  = blockIdx.x & 15;
    const int c   = cg * 4 + sub;
    const int b   = bh >> 4;
    const int h   = bh & 15;

    const float f  = freqs[h * ND + d];
    const float g0 = gate[2 * h];
    const float g1 = gate[2 * h + 1];
    const int t0 = c * LCH;

    float Pre = 0.f, Pim = 0.f, Are = 0.f, Aim = 0.f;
    const float4* pp = g_part + ((size_t)bh * NCH * ND + d);
    for (int cc = 0; cc < c; cc++) {
        float4 p = pp[(size_t)cc * ND];
        Pre += p.x; Pim += p.y; Are += p.z; Aim += p.w;
    }

    float pc = 0.f, ps = 0.f;
    if (t0 > 0) {
        float th = PHASE_SCALE * g_K[((size_t)(b * TT + t0 - 1)) * HD + h * ND + d];
        sincosf(th, &ps, &pc);
    }

    size_t base = ((size_t)(b * TT + t0)) * HD + h * ND + d;
    for (int i = 0; i < LCH; i++) {
        float v  = g_V[base];
        float kr = g_K[base];
        Are += v * pc;
        Aim -= v * ps;
        float ks, kc;
        sincosf(PHASE_SCALE * kr, &ks, &kc);
        float oa = Are * kc - Aim * ks;
        pc = kc; ps = ks;
        float sr, cr;
        sincosf((float)(t0 + i) * f, &sr, &cr);
        Pre += v * cr;
        Pim += v * sr;
        float op = Pre * cr + Pim * sr;
        int t = t0 + i;
        float o = (g0 * op + g1 * oa) * rsqrtf((float)(t + 1));
        float rem;
        g_ahi[base] = bf_hi(o, rem);
        g_alo[base] = bf_of(rem);
        base += HD;
    }
}

// ---------------------------------------------------------------------------
extern "C" void kernel_launch(void* const* d_in, const int* in_sizes, int n_in,
                              void* d_out, int out_size)
{
    const float* x     = (const float*)d_in[0];
    const float* Wk    = (const float*)d_in[1];
    const float* Wv    = (const float*)d_in[2];
    const float* Wo    = (const float*)d_in[3];
    const float* gate  = (const float*)d_in[4];
    const float* freqs = (const float*)d_in[5];
    float* out = (float*)d_out;

    float *pK, *pV;
    unsigned short *pahi, *palo, *pwT;
    cudaGetSymbolAddress((void**)&pK,   g_K);
    cudaGetSymbolAddress((void**)&pV,   g_V);
    cudaGetSymbolAddress((void**)&pahi, g_ahi);
    cudaGetSymbolAddress((void**)&palo, g_alo);
    cudaGetSymbolAddress((void**)&pwT,  g_wT);

    cudaFuncSetAttribute(gemm_bf16x3,
                         cudaFuncAttributeMaxDynamicSharedMemorySize, GEMM_SMEM);

    const int WSZ = HD * DMOD;
    unsigned short* wkh = pwT + 0*WSZ; unsigned short* wkl = pwT + 1*WSZ;
    unsigned short* wvh = pwT + 2*WSZ; unsigned short* wvl = pwT + 3*WSZ;
    unsigned short* woh = pwT + 4*WSZ; unsigned short* wol = pwT + 5*WSZ;

    const int n4 = MROWS * HD / 4;
    split_hilo<<<(n4 + 255) / 256, 256>>>(x, pahi, palo, n4);
    wsplitT3<<<dim3(32, 32, 3), dim3(32, 8)>>>(Wk, Wv, Wo);

    dim3 ggemm(GN / BN, MROWS / BM);   // (8, 64)
    gemm_bf16x3<<<ggemm, 256, GEMM_SMEM>>>(pahi, palo, wkh, wkl, pK);
    gemm_bf16x3<<<ggemm, 256, GEMM_SMEM>>>(pahi, palo, wvh, wvl, pV);

    int nscan = NB * NH * (NCH / 4);     // 512
    scan_partials<<<nscan, 256>>>(freqs);
    scan_final<<<nscan, 256>>>(freqs, gate);   // writes g_ahi/g_alo directly

    gemm_bf16x3<<<ggemm, 256, GEMM_SMEM>>>(pahi, palo, woh, wol, out);
}

// round 9
// speedup vs baseline: 2.0914x; 1.0469x over previous
#include <cuda_runtime.h>
#include <cuda_bf16.h>
#include <cstdint>
#include <math.h>

// Problem constants
#define NB   2
#define TT   4096
#define NH   16
#define ND   64
#define HD   1024
#define DMOD 1024
#define MROWS (NB*TT)       // 8192
#define PHASE_SCALE 10.0f
#define LCH  64
#define NCH  64
#define GK   1024
#define GN   1024

// ---------------- scratch (device globals; no allocs allowed) ----------------
__device__ float  g_K [MROWS * HD];
__device__ float  g_V [MROWS * HD];
__device__ float4 g_part[NB * NH * NCH * ND];
__device__ unsigned short g_ahi[MROWS * HD];     // bf16 hi of A operand (x / OH)
__device__ unsigned short g_alo[MROWS * HD];     // bf16 lo
__device__ unsigned short g_wT[6][HD * DMOD];    // WkT hi/lo, WvT hi/lo, WoT hi/lo

// ---------------- PTX helpers (baseline sm_80+ features only) ----------------
__device__ __forceinline__ uint32_t s2u(const void* p) {
    uint32_t a;
    asm("{ .reg .u64 t; cvta.to.shared.u64 t, %1; cvt.u32.u64 %0, t; }" : "=r"(a) : "l"(p));
    return a;
}
__device__ __forceinline__ void cp16(uint32_t s, const void* g) {
    asm volatile("cp.async.cg.shared.global [%0], [%1], 16;" :: "r"(s), "l"(g));
}
__device__ __forceinline__ void cp_commit() {
    asm volatile("cp.async.commit_group;" ::: "memory");
}
template <int N>
__device__ __forceinline__ void cp_wait() {
    asm volatile("cp.async.wait_group %0;" :: "n"(N) : "memory");
}
__device__ __forceinline__ void ldsm4(uint32_t* r, uint32_t addr) {
    asm volatile("ldmatrix.sync.aligned.m8n8.x4.shared.b16 {%0,%1,%2,%3}, [%4];"
        : "=r"(r[0]), "=r"(r[1]), "=r"(r[2]), "=r"(r[3]) : "r"(addr));
}
__device__ __forceinline__ void mma16816(float* c, const uint32_t* a, const uint32_t* b) {
    asm volatile("mma.sync.aligned.m16n8k16.row.col.f32.bf16.bf16.f32 "
        "{%0,%1,%2,%3}, {%4,%5,%6,%7}, {%8,%9}, {%0,%1,%2,%3};"
        : "+f"(c[0]), "+f"(c[1]), "+f"(c[2]), "+f"(c[3])
        : "r"(a[0]), "r"(a[1]), "r"(a[2]), "r"(a[3]), "r"(b[0]), "r"(b[1]));
}

// ---------------------------------------------------------------------------
// bf16x3 tensor-core GEMM via mma.sync:  C[M,N] = A[M,K] @ B[N,K]^T
// hi*hi + hi*lo + lo*hi (lo*lo dropped, ~2^-18 relative).
// 128x128 tile, BK=32, 256 threads, 2-stage cp.async, ONE sync per iter.
// Fragment loads BATCHED ahead of MMA runs; B loaded via ldsm.x4
// (matrices = {nt,nt+1} x {khalf0,khalf1}).
// SMEM rows padded to 80B -> conflict-free ldmatrix without swizzle.
// ---------------------------------------------------------------------------
#define BM 128
#define BN 128
#define BK 32
#define ROWB 80                       // 64B data + 16B pad
#define TILE_B  (BM * ROWB)           // 10240 B
#define STAGE_B (4 * TILE_B)          // Ahi, Alo, Bhi, Blo = 40960 B
#define GEMM_SMEM (2 * STAGE_B)       // 81920 B
#define NIT (GK / BK)                 // 32

__global__ __launch_bounds__(256, 2)
void gemm_bf16x3(const unsigned short* __restrict__ Ahi,
                 const unsigned short* __restrict__ Alo,
                 const unsigned short* __restrict__ Bhi,
                 const unsigned short* __restrict__ Blo,
                 float* __restrict__ C)
{
    extern __shared__ __align__(128) unsigned char smem[];
    const uint32_t sb = s2u(smem);

    const int tid  = threadIdx.x;
    const int lane = tid & 31;
    const int warp = tid >> 5;
    const int bm = blockIdx.y * BM;
    const int bn = blockIdx.x * BN;
    const int m0 = (warp >> 2) * 64;       // warp M offset within tile
    const int n0 = (warp & 3) * 32;        // warp N offset within tile

    const unsigned short* srcs[4] = {
        Ahi + (size_t)bm * GK, Alo + (size_t)bm * GK,
        Bhi + (size_t)bn * GK, Blo + (size_t)bn * GK };

    // per-thread staging slots: 2 chunks per tile per thread
    const int r0 = (tid + 0)   >> 2, c0i = (tid + 0)   & 3;
    const int r1 = (tid + 256) >> 2, c1i = (tid + 256) & 3;
    const uint32_t so0 = r0 * ROWB + c0i * 16;
    const uint32_t so1 = r1 * ROWB + c1i * 16;
    const size_t go0 = (size_t)r0 * GK + c0i * 8;
    const size_t go1 = (size_t)r1 * GK + c1i * 8;

    auto load_stage = [&](int s, int k0) {
        uint32_t base = sb + s * STAGE_B;
        #pragma unroll
        for (int t = 0; t < 4; t++) {
            cp16(base + t * TILE_B + so0, srcs[t] + go0 + k0);
            cp16(base + t * TILE_B + so1, srcs[t] + go1 + k0);
        }
        cp_commit();
    };

    float acc[4][4][4];
    #pragma unroll
    for (int i = 0; i < 4; i++)
        #pragma unroll
        for (int j = 0; j < 4; j++)
            #pragma unroll
            for (int k = 0; k < 4; k++) acc[i][j][k] = 0.f;

    // A ldsm.x4 per-lane base: rows m0+(lane&15), khalf col (lane>>4)*16
    const uint32_t a_off = (m0 + (lane & 15)) * ROWB + (lane >> 4) * 16;
    // B ldsm.x4 per-lane base: matrices = (nt_pair, khalf):
    //   lanes 0-7 ->(nt0,k0) 8-15 ->(nt0,k1) 16-23 ->(nt1,k0) 24-31 ->(nt1,k1)
    const uint32_t b_off = (n0 + (lane >> 4) * 8 + (lane & 7)) * ROWB
                         + ((lane >> 3) & 1) * 16;

    load_stage(0, 0);

    #pragma unroll 2
    for (int it = 0; it < NIT; it++) {
        cp_wait<0>();
        __syncthreads();
        if (it + 1 < NIT) load_stage((it + 1) & 1, (it + 1) * BK);

        const uint32_t stg = sb + (it & 1) * STAGE_B;
        const uint32_t sAh = stg + a_off;
        const uint32_t sAl = stg + TILE_B + a_off;
        const uint32_t sBh = stg + 2 * TILE_B + b_off;
        const uint32_t sBl = stg + 3 * TILE_B + b_off;

        #pragma unroll
        for (int kk = 0; kk < 2; kk++) {
            const uint32_t kb = kk * 32;            // byte offset of this k16
            // ---- batched B loads: 4x ldsm.x4 covers all nt, both khalves
            uint32_t bh[8], bl[8];
            ldsm4(bh + 0, sBh + kb);                 // nt 0,1
            ldsm4(bh + 4, sBh + kb + 16 * ROWB);     // nt 2,3
            ldsm4(bl + 0, sBl + kb);
            ldsm4(bl + 4, sBl + kb + 16 * ROWB);
            #pragma unroll
            for (int mp = 0; mp < 2; mp++) {
                // ---- batched A loads for mt pair {2mp, 2mp+1}
                uint32_t ah[8], al[8];
                ldsm4(ah + 0, sAh + kb + (2 * mp + 0) * (16 * ROWB));
                ldsm4(ah + 4, sAh + kb + (2 * mp + 1) * (16 * ROWB));
                ldsm4(al + 0, sAl + kb + (2 * mp + 0) * (16 * ROWB));
                ldsm4(al + 4, sAl + kb + (2 * mp + 1) * (16 * ROWB));
                // ---- clean run of 24 MMAs
                #pragma unroll
                for (int mi = 0; mi < 2; mi++) {
                    const int mt = 2 * mp + mi;
                    #pragma unroll
                    for (int nt = 0; nt < 4; nt++) {
                        const uint32_t* bph = bh + (nt >> 1) * 4 + (nt & 1) * 2;
                        const uint32_t* bpl = bl + (nt >> 1) * 4 + (nt & 1) * 2;
                        mma16816(acc[mt][nt], ah + 4 * mi, bph);   // hi*hi
                        mma16816(acc[mt][nt], ah + 4 * mi, bpl);   // hi*lo
                        mma16816(acc[mt][nt], al + 4 * mi, bph);   // lo*hi
                    }
                }
            }
        }
    }

    // epilogue: c layout m16n8 -> thread (lane/4, (lane%4)*2), rows +0/+8
    #pragma unroll
    for (int mt = 0; mt < 4; mt++) {
        const int m = bm + m0 + mt * 16 + (lane >> 2);
        #pragma unroll
        for (int nt = 0; nt < 4; nt++) {
            const int n = bn + n0 + nt * 8 + (lane & 3) * 2;
            *(float2*)&C[(size_t)m * GN + n] =
                make_float2(acc[mt][nt][0], acc[mt][nt][1]);
            *(float2*)&C[(size_t)(m + 8) * GN + n] =
                make_float2(acc[mt][nt][2], acc[mt][nt][3]);
        }
    }
}

// ---------------------------------------------------------------------------
// fp32 -> bf16 hi/lo split helpers
// ---------------------------------------------------------------------------
__device__ __forceinline__ unsigned short bf_hi(float x, float& rem) {
    __nv_bfloat16 h = __float2bfloat16_rn(x);
    rem = x - __bfloat162float(h);
    return *reinterpret_cast<unsigned short*>(&h);
}
__device__ __forceinline__ unsigned short bf_of(float x) {
    __nv_bfloat16 h = __float2bfloat16_rn(x);
    return *reinterpret_cast<unsigned short*>(&h);
}

__global__ void split_hilo(const float* __restrict__ src,
                           unsigned short* __restrict__ hi,
                           unsigned short* __restrict__ lo, int n4)
{
    int i = blockIdx.x * blockDim.x + threadIdx.x;
    if (i >= n4) return;
    float4 v = ((const float4*)src)[i];
    float r0, r1, r2, r3;
    unsigned short h0 = bf_hi(v.x, r0), h1 = bf_hi(v.y, r1);
    unsigned short h2 = bf_hi(v.z, r2), h3 = bf_hi(v.w, r3);
    ((uint2*)hi)[i] = make_uint2((uint32_t)h0 | ((uint32_t)h1 << 16),
                                (uint32_t)h2 | ((uint32_t)h3 << 16));
    unsigned short l0 = bf_of(r0), l1 = bf_of(r1), l2 = bf_of(r2), l3 = bf_of(r3);
    ((uint2*)lo)[i] = make_uint2((uint32_t)l0 | ((uint32_t)l1 << 16),
                                (uint32_t)l2 | ((uint32_t)l3 << 16));
}

// W [K,N] fp32 -> WT [N,K] bf16 hi/lo; blockIdx.z selects {Wk,Wv,Wo}
__global__ void wsplitT3(const float* __restrict__ W0,
                         const float* __restrict__ W1,
                         const float* __restrict__ W2)
{
    __shared__ float tile[32][33];
    const float* W = (blockIdx.z == 0) ? W0 : (blockIdx.z == 1) ? W1 : W2;
    unsigned short* hiT = &g_wT[2 * blockIdx.z][0];
    unsigned short* loT = &g_wT[2 * blockIdx.z + 1][0];
    int n0 = blockIdx.x * 32, k0 = blockIdx.y * 32;
    int tx = threadIdx.x, ty = threadIdx.y;
    for (int r = ty; r < 32; r += 8)
        tile[r][tx] = W[(size_t)(k0 + r) * GN + n0 + tx];
    __syncthreads();
    for (int r = ty; r < 32; r += 8) {
        float v = tile[tx][r];                    // W[k0+tx][n0+r]
        size_t o = (size_t)(n0 + r) * GK + k0 + tx;
        float rem;
        hiT[o] = bf_hi(v, rem);
        loT[o] = bf_of(rem);
    }
}

// ---------------------------------------------------------------------------
// Scan pass A: per-chunk partial complex sums
// ---------------------------------------------------------------------------
__global__ void scan_partials(const float* __restrict__ freqs)
{
    const int tid = threadIdx.x;
    const int d   = tid & 63;
    const int sub = tid >> 6;
    const int bh  = blockIdx.x >> 4;
    const int cg  = blockIdx.x & 15;
    const int c   = cg * 4 + sub;
    const int b   = bh >> 4;
    const int h   = bh & 15;

    const float f = freqs[h * ND + d];
    const int t0 = c * LCH;

    float pc = 0.f, ps = 0.f;
    if (t0 > 0) {
        float th = PHASE_SCALE * g_K[((size_t)(b * TT + t0 - 1)) * HD + h * ND + d];
        sincosf(th, &ps, &pc);
    }

    float Pre = 0.f, Pim = 0.f, Are = 0.f, Aim = 0.f;
    size_t base = ((size_t)(b * TT + t0)) * HD + h * ND + d;
    for (int i = 0; i < LCH; i++) {
        float v  = g_V[base];
        float kr = g_K[base];
        base += HD;
        Are += v * pc;
        Aim -= v * ps;
        float ks, kc;
        sincosf(PHASE_SCALE * kr, &ks, &kc);
        pc = kc; ps = ks;
        float sr, cr;
        sincosf((float)(t0 + i) * f, &sr, &cr);
        Pre += v * cr;
        Pim += v * sr;
    }
    g_part[((size_t)bh * NCH + c) * ND + d] = make_float4(Pre, Pim, Are, Aim);
}

// ---------------------------------------------------------------------------
// Scan pass B: exclusive offsets + final gated output, written directly as
// bf16 hi/lo (fused OH split -> feeds the Wo GEMM without an fp32 pass)
// ---------------------------------------------------------------------------
__global__ void scan_final(const float* __restrict__ freqs,
                           const float* __restrict__ gate)
{
    const int tid = threadIdx.x;
    const int d   = tid & 63;
    const int sub = tid >> 6;
    const int bh  = blockIdx.x >> 4;
    const int cg  = blockIdx.x & 15;
    const int c   = cg * 4 + sub;
    const int b   = bh >> 4;
    const int h   = bh & 15;

    const float f  = freqs[h * ND + d];
    const float g0 = gate[2 * h];
    const float g1 = gate[2 * h + 1];
    const int t0 = c * LCH;

    float Pre = 0.f, Pim = 0.f, Are = 0.f, Aim = 0.f;
    const float4* pp = g_part + ((size_t)bh * NCH * ND + d);
    for (int cc = 0; cc < c; cc++) {
        float4 p = pp[(size_t)cc * ND];
        Pre += p.x; Pim += p.y; Are += p.z; Aim += p.w;
    }

    float pc = 0.f, ps = 0.f;
    if (t0 > 0) {
        float th = PHASE_SCALE * g_K[((size_t)(b * TT + t0 - 1)) * HD + h * ND + d];
        sincosf(th, &ps, &pc);
    }

    size_t base = ((size_t)(b * TT + t0)) * HD + h * ND + d;
    for (int i = 0; i < LCH; i++) {
        float v  = g_V[base];
        float kr = g_K[base];
        Are += v * pc;
        Aim -= v * ps;
        float ks, kc;
        sincosf(PHASE_SCALE * kr, &ks, &kc);
        float oa = Are * kc - Aim * ks;
        pc = kc; ps = ks;
        float sr, cr;
        sincosf((float)(t0 + i) * f, &sr, &cr);
        Pre += v * cr;
        Pim += v * sr;
        float op = Pre * cr + Pim * sr;
        int t = t0 + i;
        float o = (g0 * op + g1 * oa) * rsqrtf((float)(t + 1));
        float rem;
        g_ahi[base] = bf_hi(o, rem);
        g_alo[base] = bf_of(rem);
        base += HD;
    }
}

// ---------------------------------------------------------------------------
extern "C" void kernel_launch(void* const* d_in, const int* in_sizes, int n_in,
                              void* d_out, int out_size)
{
    const float* x     = (const float*)d_in[0];
    const float* Wk    = (const float*)d_in[1];
    const float* Wv    = (const float*)d_in[2];
    const float* Wo    = (const float*)d_in[3];
    const float* gate  = (const float*)d_in[4];
    const float* freqs = (const float*)d_in[5];
    float* out = (float*)d_out;

    float *pK, *pV;
    unsigned short *pahi, *palo, *pwT;
    cudaGetSymbolAddress((void**)&pK,   g_K);
    cudaGetSymbolAddress((void**)&pV,   g_V);
    cudaGetSymbolAddress((void**)&pahi, g_ahi);
    cudaGetSymbolAddress((void**)&palo, g_alo);
    cudaGetSymbolAddress((void**)&pwT,  g_wT);

    cudaFuncSetAttribute(gemm_bf16x3,
                         cudaFuncAttributeMaxDynamicSharedMemorySize, GEMM_SMEM);

    const int WSZ = HD * DMOD;
    unsigned short* wkh = pwT + 0*WSZ; unsigned short* wkl = pwT + 1*WSZ;
    unsigned short* wvh = pwT + 2*WSZ; unsigned short* wvl = pwT + 3*WSZ;
    unsigned short* woh = pwT + 4*WSZ; unsigned short* wol = pwT + 5*WSZ;

    const int n4 = MROWS * HD / 4;
    split_hilo<<<(n4 + 255) / 256, 256>>>(x, pahi, palo, n4);
    wsplitT3<<<dim3(32, 32, 3), dim3(32, 8)>>>(Wk, Wv, Wo);

    dim3 ggemm(GN / BN, MROWS / BM);   // (8, 64)
    gemm_bf16x3<<<ggemm, 256, GEMM_SMEM>>>(pahi, palo, wkh, wkl, pK);
    gemm_bf16x3<<<ggemm, 256, GEMM_SMEM>>>(pahi, palo, wvh, wvl, pV);

    int nscan = NB * NH * (NCH / 4);     // 512
    scan_partials<<<nscan, 256>>>(freqs);
    scan_final<<<nscan, 256>>>(freqs, gate);   // writes g_ahi/g_alo directly

    gemm_bf16x3<<<ggemm, 256, GEMM_SMEM>>>(pahi, palo, woh, wol, out);
}

// round 10
// speedup vs baseline: 2.1339x; 1.0203x over previous
#include <cuda_runtime.h>
#include <cuda_bf16.h>
#include <cstdint>
#include <math.h>

// Problem constants
#define NB   2
#define TT   4096
#define NH   16
#define ND   64
#define HD   1024
#define DMOD 1024
#define MROWS (NB*TT)       // 8192
#define PHASE_SCALE 10.0f
#define LCH  32             // chunk length for the scan
#define NCH  128            // number of chunks (LCH*NCH == TT)
#define GK   1024
#define GN   1024

// ---------------- scratch (device globals; no allocs allowed) ----------------
__device__ float  g_K [MROWS * HD];
__device__ float  g_V [MROWS * HD];
__device__ float4 g_part[NB * NH * NCH * ND];
__device__ unsigned short g_ahi[MROWS * HD];     // bf16 hi of A operand (x / OH)
__device__ unsigned short g_alo[MROWS * HD];     // bf16 lo
__device__ unsigned short g_wT[6][HD * DMOD];    // WkT hi/lo, WvT hi/lo, WoT hi/lo

// ---------------- PTX helpers (baseline sm_80+ features only) ----------------
__device__ __forceinline__ uint32_t s2u(const void* p) {
    uint32_t a;
    asm("{ .reg .u64 t; cvta.to.shared.u64 t, %1; cvt.u32.u64 %0, t; }" : "=r"(a) : "l"(p));
    return a;
}
__device__ __forceinline__ void cp16(uint32_t s, const void* g) {
    asm volatile("cp.async.cg.shared.global [%0], [%1], 16;" :: "r"(s), "l"(g));
}
__device__ __forceinline__ void cp_commit() {
    asm volatile("cp.async.commit_group;" ::: "memory");
}
template <int N>
__device__ __forceinline__ void cp_wait() {
    asm volatile("cp.async.wait_group %0;" :: "n"(N) : "memory");
}
__device__ __forceinline__ void ldsm4(uint32_t* r, uint32_t addr) {
    asm volatile("ldmatrix.sync.aligned.m8n8.x4.shared.b16 {%0,%1,%2,%3}, [%4];"
        : "=r"(r[0]), "=r"(r[1]), "=r"(r[2]), "=r"(r[3]) : "r"(addr));
}
__device__ __forceinline__ void mma16816(float* c, const uint32_t* a, const uint32_t* b) {
    asm volatile("mma.sync.aligned.m16n8k16.row.col.f32.bf16.bf16.f32 "
        "{%0,%1,%2,%3}, {%4,%5,%6,%7}, {%8,%9}, {%0,%1,%2,%3};"
        : "+f"(c[0]), "+f"(c[1]), "+f"(c[2]), "+f"(c[3])
        : "r"(a[0]), "r"(a[1]), "r"(a[2]), "r"(a[3]), "r"(b[0]), "r"(b[1]));
}

// ---------------------------------------------------------------------------
// bf16x3 tensor-core GEMM via mma.sync:  C[M,N] = A[M,K] @ B[N,K]^T
// hi*hi + hi*lo + lo*hi (lo*lo dropped, ~2^-18 relative).
// 128x128 tile, BK=32, 256 threads, 2-stage cp.async, ONE sync per iter.
// MMAs issued TERM-MAJOR: same-accumulator dependency distance = 8 MMAs
// (the round-9 version chained all 3 terms back-to-back on each acc).
// SMEM rows padded to 80B -> conflict-free ldmatrix without swizzle.
// ---------------------------------------------------------------------------
#define BM 128
#define BN 128
#define BK 32
#define ROWB 80                       // 64B data + 16B pad
#define TILE_B  (BM * ROWB)           // 10240 B
#define STAGE_B (4 * TILE_B)          // Ahi, Alo, Bhi, Blo = 40960 B
#define GEMM_SMEM (2 * STAGE_B)       // 81920 B
#define NIT (GK / BK)                 // 32

__global__ __launch_bounds__(256, 2)
void gemm_bf16x3(const unsigned short* __restrict__ Ahi,
                 const unsigned short* __restrict__ Alo,
                 const unsigned short* __restrict__ Bhi,
                 const unsigned short* __restrict__ Blo,
                 float* __restrict__ C)
{
    extern __shared__ __align__(128) unsigned char smem[];
    const uint32_t sb = s2u(smem);

    const int tid  = threadIdx.x;
    const int lane = tid & 31;
    const int warp = tid >> 5;
    const int bm = blockIdx.y * BM;
    const int bn = blockIdx.x * BN;
    const int m0 = (warp >> 2) * 64;       // warp M offset within tile
    const int n0 = (warp & 3) * 32;        // warp N offset within tile

    const unsigned short* srcs[4] = {
        Ahi + (size_t)bm * GK, Alo + (size_t)bm * GK,
        Bhi + (size_t)bn * GK, Blo + (size_t)bn * GK };

    // per-thread staging slots: 2 chunks per tile per thread
    const int r0 = (tid + 0)   >> 2, c0i = (tid + 0)   & 3;
    const int r1 = (tid + 256) >> 2, c1i = (tid + 256) & 3;
    const uint32_t so0 = r0 * ROWB + c0i * 16;
    const uint32_t so1 = r1 * ROWB + c1i * 16;
    const size_t go0 = (size_t)r0 * GK + c0i * 8;
    const size_t go1 = (size_t)r1 * GK + c1i * 8;

    auto load_stage = [&](int s, int k0) {
        uint32_t base = sb + s * STAGE_B;
        #pragma unroll
        for (int t = 0; t < 4; t++) {
            cp16(base + t * TILE_B + so0, srcs[t] + go0 + k0);
            cp16(base + t * TILE_B + so1, srcs[t] + go1 + k0);
        }
        cp_commit();
    };

    float acc[4][4][4];
    #pragma unroll
    for (int i = 0; i < 4; i++)
        #pragma unroll
        for (int j = 0; j < 4; j++)
            #pragma unroll
            for (int k = 0; k < 4; k++) acc[i][j][k] = 0.f;

    // A ldsm.x4 per-lane base: rows m0+(lane&15), khalf col (lane>>4)*16
    const uint32_t a_off = (m0 + (lane & 15)) * ROWB + (lane >> 4) * 16;
    // B ldsm.x4 per-lane base: matrices = (nt_pair, khalf)
    const uint32_t b_off = (n0 + (lane >> 4) * 8 + (lane & 7)) * ROWB
                         + ((lane >> 3) & 1) * 16;

    load_stage(0, 0);

    #pragma unroll 2
    for (int it = 0; it < NIT; it++) {
        cp_wait<0>();
        __syncthreads();
        if (it + 1 < NIT) load_stage((it + 1) & 1, (it + 1) * BK);

        const uint32_t stg = sb + (it & 1) * STAGE_B;
        const uint32_t sAh = stg + a_off;
        const uint32_t sAl = stg + TILE_B + a_off;
        const uint32_t sBh = stg + 2 * TILE_B + b_off;
        const uint32_t sBl = stg + 3 * TILE_B + b_off;

        #pragma unroll
        for (int kk = 0; kk < 2; kk++) {
            const uint32_t kb = kk * 32;            // byte offset of this k16
            // batched B loads: 4x ldsm.x4 covers all nt, both khalves
            uint32_t bh[8], bl[8];
            ldsm4(bh + 0, sBh + kb);                 // nt 0,1
            ldsm4(bh + 4, sBh + kb + 16 * ROWB);     // nt 2,3
            ldsm4(bl + 0, sBl + kb);
            ldsm4(bl + 4, sBl + kb + 16 * ROWB);
            #pragma unroll
            for (int mp = 0; mp < 2; mp++) {
                // batched A loads for mt pair {2mp, 2mp+1}
                uint32_t ah[8], al[8];
                ldsm4(ah + 0, sAh + kb + (2 * mp + 0) * (16 * ROWB));
                ldsm4(ah + 4, sAh + kb + (2 * mp + 1) * (16 * ROWB));
                ldsm4(al + 0, sAl + kb + (2 * mp + 0) * (16 * ROWB));
                ldsm4(al + 4, sAl + kb + (2 * mp + 1) * (16 * ROWB));
                // 24 MMAs, TERM-MAJOR: 8x hi*hi, 8x hi*lo, 8x lo*hi
                #pragma unroll
                for (int mi = 0; mi < 2; mi++)
                    #pragma unroll
                    for (int nt = 0; nt < 4; nt++)
                        mma16816(acc[2 * mp + mi][nt], ah + 4 * mi,
                                 bh + (nt >> 1) * 4 + (nt & 1) * 2);
                #pragma unroll
                for (int mi = 0; mi < 2; mi++)
                    #pragma unroll
                    for (int nt = 0; nt < 4; nt++)
                        mma16816(acc[2 * mp + mi][nt], ah + 4 * mi,
                                 bl + (nt >> 1) * 4 + (nt & 1) * 2);
                #pragma unroll
                for (int mi = 0; mi < 2; mi++)
                    #pragma unroll
                    for (int nt = 0; nt < 4; nt++)
                        mma16816(acc[2 * mp + mi][nt], al + 4 * mi,
                                 bh + (nt >> 1) * 4 + (nt & 1) * 2);
            }
        }
    }

    // epilogue: c layout m16n8 -> thread (lane/4, (lane%4)*2), rows +0/+8
    #pragma unroll
    for (int mt = 0; mt < 4; mt++) {
        const int m = bm + m0 + mt * 16 + (lane >> 2);
        #pragma unroll
        for (int nt = 0; nt < 4; nt++) {
            const int n = bn + n0 + nt * 8 + (lane & 3) * 2;
            *(float2*)&C[(size_t)m * GN + n] =
                make_float2(acc[mt][nt][0], acc[mt][nt][1]);
            *(float2*)&C[(size_t)(m + 8) * GN + n] =
                make_float2(acc[mt][nt][2], acc[mt][nt][3]);
        }
    }
}

// ---------------------------------------------------------------------------
// fp32 -> bf16 hi/lo split helpers
// ---------------------------------------------------------------------------
__device__ __forceinline__ unsigned short bf_hi(float x, float& rem) {
    __nv_bfloat16 h = __float2bfloat16_rn(x);
    rem = x - __bfloat162float(h);
    return *reinterpret_cast<unsigned short*>(&h);
}
__device__ __forceinline__ unsigned short bf_of(float x) {
    __nv_bfloat16 h = __float2bfloat16_rn(x);
    return *reinterpret_cast<unsigned short*>(&h);
}

__global__ void split_hilo(const float* __restrict__ src,
                           unsigned short* __restrict__ hi,
                           unsigned short* __restrict__ lo, int n4)
{
    int i = blockIdx.x * blockDim.x + threadIdx.x;
    if (i >= n4) return;
    float4 v = ((const float4*)src)[i];
    float r0, r1, r2, r3;
    unsigned short h0 = bf_hi(v.x, r0), h1 = bf_hi(v.y, r1);
    unsigned short h2 = bf_hi(v.z, r2), h3 = bf_hi(v.w, r3);
    ((uint2*)hi)[i] = make_uint2((uint32_t)h0 | ((uint32_t)h1 << 16),
                                (uint32_t)h2 | ((uint32_t)h3 << 16));
    unsigned short l0 = bf_of(r0), l1 = bf_of(r1), l2 = bf_of(r2), l3 = bf_of(r3);
    ((uint2*)lo)[i] = make_uint2((uint32_t)l0 | ((uint32_t)l1 << 16),
                                (uint32_t)l2 | ((uint32_t)l3 << 16));
}

// W [K,N] fp32 -> WT [N,K] bf16 hi/lo; blockIdx.z selects {Wk,Wv,Wo}
__global__ void wsplitT3(const float* __restrict__ W0,
                         const float* __restrict__ W1,
                         const float* __restrict__ W2)
{
    __shared__ float tile[32][33];
    const float* W = (blockIdx.z == 0) ? W0 : (blockIdx.z == 1) ? W1 : W2;
    unsigned short* hiT = &g_wT[2 * blockIdx.z][0];
    unsigned short* loT = &g_wT[2 * blockIdx.z + 1][0];
    int n0 = blockIdx.x * 32, k0 = blockIdx.y * 32;
    int tx = threadIdx.x, ty = threadIdx.y;
    for (int r = ty; r < 32; r += 8)
        tile[r][tx] = W[(size_t)(k0 + r) * GN + n0 + tx];
    __syncthreads();
    for (int r = ty; r < 32; r += 8) {
        float v = tile[tx][r];                    // W[k0+tx][n0+r]
        size_t o = (size_t)(n0 + r) * GK + k0 + tx;
        float rem;
        hiT[o] = bf_hi(v, rem);
        loT[o] = bf_of(rem);
    }
}

// ---------------------------------------------------------------------------
// Scan pass A: per-chunk partial complex sums. LCH=32, NCH=128 ->
// 1024 blocks (2x round-9 parallelism; scans were latency-bound).
// grid: NB*NH*(NCH/4) blocks, 256 threads = 64 d-lanes x 4 chunks
// ---------------------------------------------------------------------------
__global__ void scan_partials(const float* __restrict__ freqs)
{
    const int tid = threadIdx.x;
    const int d   = tid & 63;
    const int sub = tid >> 6;
    const int bh  = blockIdx.x >> 5;     // NCH/4 = 32 groups per (b,h)
    const int cg  = blockIdx.x & 31;
    const int c   = cg * 4 + sub;
    const int b   = bh >> 4;
    const int h   = bh & 15;

    const float f = freqs[h * ND + d];
    const int t0 = c * LCH;

    float pc = 0.f, ps = 0.f;
    if (t0 > 0) {
        float th = PHASE_SCALE * g_K[((size_t)(b * TT + t0 - 1)) * HD + h * ND + d];
        sincosf(th, &ps, &pc);
    }

    float Pre = 0.f, Pim = 0.f, Are = 0.f, Aim = 0.f;
    size_t base = ((size_t)(b * TT + t0)) * HD + h * ND + d;
    for (int i = 0; i < LCH; i++) {
        float v  = g_V[base];
        float kr = g_K[base];
        base += HD;
        Are += v * pc;
        Aim -= v * ps;
        float ks, kc;
        sincosf(PHASE_SCALE * kr, &ks, &kc);
        pc = kc; ps = ks;
        float sr, cr;
        sincosf((float)(t0 + i) * f, &sr, &cr);
        Pre += v * cr;
        Pim += v * sr;
    }
    g_part[((size_t)bh * NCH + c) * ND + d] = make_float4(Pre, Pim, Are, Aim);
}

// ---------------------------------------------------------------------------
// Scan pass B: exclusive offsets + final gated output, written directly as
// bf16 hi/lo (fused OH split -> feeds the Wo GEMM without an fp32 pass)
// ---------------------------------------------------------------------------
__global__ void scan_final(const float* __restrict__ freqs,
                           const float* __restrict__ gate)
{
    const int tid = threadIdx.x;
    const int d   = tid & 63;
    const int sub = tid >> 6;
    const int bh  = blockIdx.x >> 5;
    const int cg  = blockIdx.x & 31;
    const int c   = cg * 4 + sub;
    const int b   = bh >> 4;
    const int h   = bh & 15;

    const float f  = freqs[h * ND + d];
    const float g0 = gate[2 * h];
    const float g1 = gate[2 * h + 1];
    const int t0 = c * LCH;

    float Pre = 0.f, Pim = 0.f, Are = 0.f, Aim = 0.f;
    const float4* pp = g_part + ((size_t)bh * NCH * ND + d);
    for (int cc = 0; cc < c; cc++) {
        float4 p = pp[(size_t)cc * ND];
        Pre += p.x; Pim += p.y; Are += p.z; Aim += p.w;
    }

    float pc = 0.f, ps = 0.f;
    if (t0 > 0) {
        float th = PHASE_SCALE * g_K[((size_t)(b * TT + t0 - 1)) * HD + h * ND + d];
        sincosf(th, &ps, &pc);
    }

    size_t base = ((size_t)(b * TT + t0)) * HD + h * ND + d;
    for (int i = 0; i < LCH; i++) {
        float v  = g_V[base];
        float kr = g_K[base];
        Are += v * pc;
        Aim -= v * ps;
        float ks, kc;
        sincosf(PHASE_SCALE * kr, &ks, &kc);
        float oa = Are * kc - Aim * ks;
        pc = kc; ps = ks;
        float sr, cr;
        sincosf((float)(t0 + i) * f, &sr, &cr);
        Pre += v * cr;
        Pim += v * sr;
        float op = Pre * cr + Pim * sr;
        int t = t0 + i;
        float o = (g0 * op + g1 * oa) * rsqrtf((float)(t + 1));
        float rem;
        g_ahi[base] = bf_hi(o, rem);
        g_alo[base] = bf_of(rem);
        base += HD;
    }
}

// ---------------------------------------------------------------------------
extern "C" void kernel_launch(void* const* d_in, const int* in_sizes, int n_in,
                              void* d_out, int out_size)
{
    const float* x     = (const float*)d_in[0];
    const float* Wk    = (const float*)d_in[1];
    const float* Wv    = (const float*)d_in[2];
    const float* Wo    = (const float*)d_in[3];
    const float* gate  = (const float*)d_in[4];
    const float* freqs = (const float*)d_in[5];
    float* out = (float*)d_out;

    float *pK, *pV;
    unsigned short *pahi, *palo, *pwT;
    cudaGetSymbolAddress((void**)&pK,   g_K);
    cudaGetSymbolAddress((void**)&pV,   g_V);
    cudaGetSymbolAddress((void**)&pahi, g_ahi);
    cudaGetSymbolAddress((void**)&palo, g_alo);
    cudaGetSymbolAddress((void**)&pwT,  g_wT);

    cudaFuncSetAttribute(gemm_bf16x3,
                         cudaFuncAttributeMaxDynamicSharedMemorySize, GEMM_SMEM);

    const int WSZ = HD * DMOD;
    unsigned short* wkh = pwT + 0*WSZ; unsigned short* wkl = pwT + 1*WSZ;
    unsigned short* wvh = pwT + 2*WSZ; unsigned short* wvl = pwT + 3*WSZ;
    unsigned short* woh = pwT + 4*WSZ; unsigned short* wol = pwT + 5*WSZ;

    const int n4 = MROWS * HD / 4;
    split_hilo<<<(n4 + 255) / 256, 256>>>(x, pahi, palo, n4);
    wsplitT3<<<dim3(32, 32, 3), dim3(32, 8)>>>(Wk, Wv, Wo);

    dim3 ggemm(GN / BN, MROWS / BM);   // (8, 64)
    gemm_bf16x3<<<ggemm, 256, GEMM_SMEM>>>(pahi, palo, wkh, wkl, pK);
    gemm_bf16x3<<<ggemm, 256, GEMM_SMEM>>>(pahi, palo, wvh, wvl, pV);

    int nscan = NB * NH * (NCH / 4);     // 1024
    scan_partials<<<nscan, 256>>>(freqs);
    scan_final<<<nscan, 256>>>(freqs, gate);   // writes g_ahi/g_alo directly

    gemm_bf16x3<<<ggemm, 256, GEMM_SMEM>>>(pahi, palo, woh, wol, out);
}